// round 14
// baseline (speedup 1.0000x reference)
#include <cuda_runtime.h>

// CapsuleLayer dynamic routing, fully fused. Round 14: c-split warp pairs.
// Each warp: 4 b's x 8 c's -> 32 accumulator regs -> 3 CTAs/SM (24 warps).
// Warp pair (even: c0-7, odd: c8-15) exchanges s/Z partials via smem + named
// barrier (3 per kernel). Deferred-Z softmax; tr8 transpose-reduce.
// Shapes: B=64, R=2048, C=16, O=32, I=16. 3 routing iterations.
// Grid: (4, 2048): x = b-quarter (16 b's), y = r. CTA = 256 threads = 8 warps.

#define FULLM 0xffffffffu

static __device__ __forceinline__ float2 ffma2(float2 a, float2 b, float2 c) {
    unsigned long long ua = *reinterpret_cast<unsigned long long*>(&a);
    unsigned long long ub = *reinterpret_cast<unsigned long long*>(&b);
    unsigned long long uc = *reinterpret_cast<unsigned long long*>(&c);
    unsigned long long ud;
    asm("fma.rn.f32x2 %0, %1, %2, %3;" : "=l"(ud) : "l"(ua), "l"(ub), "l"(uc));
    return *reinterpret_cast<float2*>(&ud);
}
static __device__ __forceinline__ float2 add2(float2 a, float2 b) {
    unsigned long long ua = *reinterpret_cast<unsigned long long*>(&a);
    unsigned long long ub = *reinterpret_cast<unsigned long long*>(&b);
    unsigned long long ud;
    asm("add.rn.f32x2 %0, %1, %2;" : "=l"(ud) : "l"(ua), "l"(ub));
    return *reinterpret_cast<float2*>(&ud);
}
static __device__ __forceinline__ float2 mul2(float2 a, float2 b) {
    unsigned long long ua = *reinterpret_cast<unsigned long long*>(&a);
    unsigned long long ub = *reinterpret_cast<unsigned long long*>(&b);
    unsigned long long ud;
    asm("mul.rn.f32x2 %0, %1, %2;" : "=l"(ud) : "l"(ua), "l"(ub));
    return *reinterpret_cast<float2*>(&ud);
}
static __device__ __forceinline__ float2 pack2(float x) {
    unsigned long long r;
    asm("mov.b64 %0, {%1, %1};" : "=l"(r) : "f"(x));
    return *reinterpret_cast<float2*>(&r);
}
static __device__ __forceinline__ float rcp_approx(float x) {
    float r; asm("rcp.approx.f32 %0, %1;" : "=f"(r) : "f"(x)); return r;
}
static __device__ __forceinline__ float sqrt_approx(float x) {
    float r; asm("sqrt.approx.f32 %0, %1;" : "=f"(r) : "f"(x)); return r;
}
static __device__ __forceinline__ float2 shfl_xor2(float2 v, int m) {
    v.x = __shfl_xor_sync(FULLM, v.x, m);
    v.y = __shfl_xor_sync(FULLM, v.y, m);
    return v;
}
static __device__ __forceinline__ void cp_async16(unsigned dst_smem, const void* src) {
    asm volatile("cp.async.ca.shared.global [%0], [%1], 16;" :: "r"(dst_smem), "l"(src));
}
static __device__ __forceinline__ void bar_pair(int id) {
    asm volatile("bar.sync %0, 64;" :: "r"(id) : "memory");
}

// squash factor: fac = sqrt(n)/(1+n), n = sum over o(=32 lanes) of s^2. f32x2/b-pair.
static __device__ __forceinline__ float2 normfac(float2 s) {
    float2 n = mul2(s, s);
#pragma unroll
    for (int m = 16; m >= 1; m >>= 1) n = add2(n, shfl_xor2(n, m));
    return make_float2(sqrt_approx(n.x) * rcp_approx(1.0f + n.x),
                       sqrt_approx(n.y) * rcp_approx(1.0f + n.y));
}

// tr8: r[lane] = Sum_o U[lane%8][o] * v[o]  (o = lanes), replicated x4.
// 9 shfl_xor2 total.
static __device__ __forceinline__ float2 tr8(const float2* __restrict__ U,
                                             float2 v, int lane) {
    const int q0 = lane & 1, q1 = (lane >> 1) & 1, q2 = (lane >> 2) & 1;
    float2 a[4];
#pragma unroll
    for (int k = 0; k < 4; k++) {
        float2 keep = mul2(q0 ? U[2 * k + 1] : U[2 * k], v);
        float2 give = mul2(q0 ? U[2 * k] : U[2 * k + 1], v);
        a[k] = add2(keep, shfl_xor2(give, 1));
    }
    float2 c0, c1;
    {
        float2 keep = q1 ? a[1] : a[0], give = q1 ? a[0] : a[1];
        c0 = add2(keep, shfl_xor2(give, 2));
        keep = q1 ? a[3] : a[2]; give = q1 ? a[2] : a[3];
        c1 = add2(keep, shfl_xor2(give, 2));
    }
    float2 d;
    {
        float2 keep = q2 ? c1 : c0, give = q2 ? c0 : c1;
        d = add2(keep, shfl_xor2(give, 4));
    }
    d = add2(d, shfl_xor2(d, 8));
    d = add2(d, shfl_xor2(d, 16));
    return d;
}

__global__ void __launch_bounds__(256, 3)
caps_routing_kernel(const float* __restrict__ x,   // [64, 2048, 16]
                    const float* __restrict__ W,   // [2048, 16, 32, 16]
                    float* __restrict__ out)       // [64, 2048, 32]
{
    const int r = blockIdx.y;
    const int b_base = blockIdx.x << 4;   // 0, 16, 32, 48
    const int tid = threadIdx.x;
    const int lane = tid & 31;            // = o
    const int wid = tid >> 5;             // 0..7
    const int pair = wid >> 1;            // 0..3 (owns 4 b's)
    const int ch = wid & 1;               // c-half: c in [8ch, 8ch+8)

    __shared__ float4 Ws4[4 * 514];              // [i4][c][o] float4, padded (32.9 KB)
    __shared__ float2 Xs[8 * 16];                // [b-pair][i] = (x_even, x_odd)
    __shared__ float2 Rbuf[4][2][2][8];          // [pair][ch][p][k] = e2 (own 8 c)
    __shared__ float2 SEx[4][2][2][32];          // [pair][ch][p][lane] s-partials
    __shared__ float2 SZ[4][2][2];               // [pair][ch][p] Z-partials

    // ---- stage W[r] (32 KB) with i4-major transpose via cp.async (contiguous src) ----
    {
        const float4* Wg4 = reinterpret_cast<const float4*>(W + (size_t)r * 8192);
        unsigned ws_base = (unsigned)__cvta_generic_to_shared(Ws4);
#pragma unroll
        for (int k = 0; k < 8; k++) {
            int f = tid + k * 256;               // [16c][32o][4 i4]
            int c = f >> 7, o = (f >> 2) & 31, i4 = f & 3;
            cp_async16(ws_base + (unsigned)((i4 * 514 + c * 32 + o) * 16), Wg4 + f);
        }
        asm volatile("cp.async.commit_group;" ::: "memory");
    }
    // ---- stage x[b_base..b_base+16, r, :] packed as b-pairs ----
    if (tid < 64) {
        int b_loc = tid >> 2, q = tid & 3;
        const float4* xg4 = reinterpret_cast<const float4*>(
            x + (size_t)(b_base + b_loc) * 32768 + (size_t)r * 16);
        float4 xv = xg4[q];
        int bp = b_loc >> 1, par = b_loc & 1;
        float* xsf = reinterpret_cast<float*>(Xs);
        xsf[((bp * 16 + q * 4 + 0) << 1) + par] = xv.x;
        xsf[((bp * 16 + q * 4 + 1) << 1) + par] = xv.y;
        xsf[((bp * 16 + q * 4 + 2) << 1) + par] = xv.z;
        xsf[((bp * 16 + q * 4 + 3) << 1) + par] = xv.w;
    }
    asm volatile("cp.async.wait_group 0;" ::: "memory");
    __syncthreads();

    // ---- u_hat: u[p][k] = f32x2 over b-pair (bp = 2*pair+p), c = 8*ch + k ----
    float2 u[2][8];
#pragma unroll
    for (int p = 0; p < 2; p++)
#pragma unroll
        for (int k = 0; k < 8; k++) u[p][k] = make_float2(0.f, 0.f);

#pragma unroll
    for (int i4 = 0; i4 < 4; i4++) {
        float2 xv[2][4];
#pragma unroll
        for (int p = 0; p < 2; p++) {
            const float4* xp = reinterpret_cast<const float4*>(
                &Xs[(2 * pair + p) * 16 + i4 * 4]);
            float4 q0 = xp[0];   // uniform (broadcast) LDS.128
            float4 q1 = xp[1];
            xv[p][0] = make_float2(q0.x, q0.y);
            xv[p][1] = make_float2(q0.z, q0.w);
            xv[p][2] = make_float2(q1.x, q1.y);
            xv[p][3] = make_float2(q1.z, q1.w);
        }
#pragma unroll
        for (int k = 0; k < 8; k++) {
            float4 w4 = Ws4[i4 * 514 + (8 * ch + k) * 32 + lane];
            float2 w0 = pack2(w4.x), w1 = pack2(w4.y), w2 = pack2(w4.z), w3 = pack2(w4.w);
#pragma unroll
            for (int p = 0; p < 2; p++) {
                u[p][k] = ffma2(w0, xv[p][0], u[p][k]);
                u[p][k] = ffma2(w1, xv[p][1], u[p][k]);
                u[p][k] = ffma2(w2, xv[p][2], u[p][k]);
                u[p][k] = ffma2(w3, xv[p][3], u[p][k]);
            }
        }
    }

    const int barid = pair + 1;

    // ---- iteration 1: route uniform -> s = (sum over all 16 c of u)/16 ----
    float2 bown[2];
    float2 v[2];
    {
        float2 sp[2];
#pragma unroll
        for (int p = 0; p < 2; p++) {
            float2 t = add2(add2(add2(u[p][0], u[p][1]), add2(u[p][2], u[p][3])),
                            add2(add2(u[p][4], u[p][5]), add2(u[p][6], u[p][7])));
            sp[p] = mul2(t, make_float2(0.0625f, 0.0625f));
            SEx[pair][ch][p][lane] = sp[p];
        }
        bar_pair(barid);
#pragma unroll
        for (int p = 0; p < 2; p++) {
            float2 s = add2(sp[p], SEx[pair][ch ^ 1][p][lane]);
            v[p] = mul2(s, normfac(s));
        }
#pragma unroll
        for (int p = 0; p < 2; p++)
            bown[p] = tr8(u[p], v[p], lane);       // logit for own c = 8ch + lane%8
    }

    // ---- iterations 2 and 3 ----
#pragma unroll
    for (int it = 0; it < 2; it++) {
        float2 stp[2], Zp[2];
#pragma unroll
        for (int p = 0; p < 2; p++) {
            float2 e2 = make_float2(__expf(bown[p].x), __expf(bown[p].y));
            __syncwarp();
            if (lane < 8) Rbuf[pair][ch][p][lane] = e2;
            __syncwarp();
            // quad-read own 8 e-pairs; s-tilde partial + Z partial (deferred-Z)
            const float4* rb = reinterpret_cast<const float4*>(&Rbuf[pair][ch][p][0]);
            float4 q0 = rb[0], q1 = rb[1], q2 = rb[2], q3 = rb[3];
            float2 ea0 = make_float2(q0.x, q0.y), ea1 = make_float2(q0.z, q0.w);
            float2 ea2 = make_float2(q1.x, q1.y), ea3 = make_float2(q1.z, q1.w);
            float2 ea4 = make_float2(q2.x, q2.y), ea5 = make_float2(q2.z, q2.w);
            float2 ea6 = make_float2(q3.x, q3.y), ea7 = make_float2(q3.z, q3.w);
            float2 sa = mul2(ea0, u[p][0]);
            float2 sb = mul2(ea1, u[p][1]);
            sa = ffma2(ea2, u[p][2], sa);
            sb = ffma2(ea3, u[p][3], sb);
            sa = ffma2(ea4, u[p][4], sa);
            sb = ffma2(ea5, u[p][5], sb);
            sa = ffma2(ea6, u[p][6], sa);
            sb = ffma2(ea7, u[p][7], sb);
            stp[p] = add2(sa, sb);
            Zp[p] = add2(add2(add2(ea0, ea1), add2(ea2, ea3)),
                         add2(add2(ea4, ea5), add2(ea6, ea7)));
            SEx[pair][ch][p][lane] = stp[p];
            if (lane == 0) SZ[pair][ch][p] = Zp[p];
        }
        bar_pair(barid);
#pragma unroll
        for (int p = 0; p < 2; p++) {
            float2 st = add2(stp[p], SEx[pair][ch ^ 1][p][lane]);
            float2 Z = add2(Zp[p], SZ[pair][ch ^ 1][p]);
            float2 rz = make_float2(rcp_approx(Z.x), rcp_approx(Z.y));
            float2 s = mul2(st, rz);
            v[p] = mul2(s, normfac(s));
        }
        if (it == 0) {
#pragma unroll
            for (int p = 0; p < 2; p++)
                bown[p] = add2(bown[p], tr8(u[p], v[p], lane));
        }
    }

    // ---- write v (both warps of pair computed identical v; ch==0 writes) ----
    if (ch == 0) {
        const int bg = b_base + pair * 4;
        float* o0 = out + (size_t)bg * 65536 + (size_t)r * 32 + lane;
        o0[0 * 65536] = v[0].x;
        o0[1 * 65536] = v[0].y;
        o0[2 * 65536] = v[1].x;
        o0[3 * 65536] = v[1].y;
    }
}

extern "C" void kernel_launch(void* const* d_in, const int* in_sizes, int n_in,
                              void* d_out, int out_size) {
    const float* x = (const float*)d_in[0];
    const float* W = (const float*)d_in[1];
    // defensive: x is the smaller input (2,097,152 vs 16,777,216 elements)
    if (n_in >= 2 && in_sizes[0] > in_sizes[1]) {
        const float* t = x; x = W; W = t;
    }
    float* out = (float*)d_out;
    dim3 grid(4, 2048);   // x = b-quarter (same-r CTAs adjacent for L2 W reuse)
    caps_routing_kernel<<<grid, 256>>>(x, W, out);
}